// round 8
// baseline (speedup 1.0000x reference)
#include <cuda_runtime.h>
#include <cuda_fp16.h>
#include <math.h>
#include <stdint.h>

#define NN   10000
#define NE   250000
#define FF   128
#define NRBF 50
#define RBFP 64

typedef unsigned long long ull;

// ---------------- scratch ----------------
__device__ float  g_x[NN * FF];
__device__ float  g_qkv[NN * 3 * 512];
__device__ __half g_rbf[(size_t)NE * RBFP];
__device__ float  g_unit[(size_t)NE * 3];
__device__ __half g_dkdv[(size_t)NE * 1024];
__device__ __half g_msg[(size_t)NE * 512];

#define FMA2(acc, a, b) asm("fma.rn.f32x2 %0, %1, %2, %0;" : "+l"(acc) : "l"(a), "l"(b))
#define PACK2(dst, f)   asm("mov.b64 %0, {%1, %1};" : "=l"(dst) : "f"(f))
#define UNPACK2(lo, hi, v) asm("mov.b64 {%0, %1}, %2;" : "=f"(lo), "=f"(hi) : "l"(v))

__device__ __forceinline__ uint32_t smem_u32(const void* p) {
    uint32_t a;
    asm("{ .reg .u64 t; cvta.to.shared.u64 t, %1; cvt.u32.u64 %0, t; }" : "=r"(a) : "l"(p));
    return a;
}
__device__ __forceinline__ float silu_f(float v) {
    return v / (1.f + __expf(-v));
}

#define MMA_F16(c, a0, a1, a2, a3, b0, b1)                                \
    asm volatile("mma.sync.aligned.m16n8k16.row.col.f32.f16.f16.f32 "     \
        "{%0,%1,%2,%3}, {%4,%5,%6,%7}, {%8,%9}, {%0,%1,%2,%3};"           \
        : "+f"((c)[0]), "+f"((c)[1]), "+f"((c)[2]), "+f"((c)[3])          \
        : "r"(a0), "r"(a1), "r"(a2), "r"(a3), "r"(b0), "r"(b1))

#define LDSM_X4(r0, r1, r2, r3, addr)                                     \
    asm volatile("ldmatrix.sync.aligned.m8n8.x4.shared.b16 {%0,%1,%2,%3}, [%4];" \
        : "=r"(r0), "=r"(r1), "=r"(r2), "=r"(r3) : "r"(addr))

#define CP_ASYNC16(dst, src) \
    asm volatile("cp.async.ca.shared.global [%0], [%1], 16;" :: "r"(dst), "l"(src))
#define CP_COMMIT() asm volatile("cp.async.commit_group;" ::: "memory")
#define CP_WAIT0()  asm volatile("cp.async.wait_group 0;" ::: "memory")

// ================= small kernels =================
__global__ void zero_kernel(float* __restrict__ p, int n) {
    int i = blockIdx.x * blockDim.x + threadIdx.x;
    if (i < n) p[i] = 0.f;
}

__global__ void __launch_bounds__(128) ln_kernel(const float* __restrict__ s,
                                                 const float* __restrict__ gam,
                                                 const float* __restrict__ bet,
                                                 float* __restrict__ x) {
    int n = blockIdx.x, t = threadIdx.x;
    float v = s[(size_t)n * FF + t];
    float s1 = v, s2 = v * v;
    #pragma unroll
    for (int o = 16; o; o >>= 1) {
        s1 += __shfl_down_sync(0xffffffffu, s1, o);
        s2 += __shfl_down_sync(0xffffffffu, s2, o);
    }
    __shared__ float p1[4], p2[4], mv[2];
    if ((t & 31) == 0) { p1[t >> 5] = s1; p2[t >> 5] = s2; }
    __syncthreads();
    if (t == 0) {
        float a = p1[0] + p1[1] + p1[2] + p1[3];
        float c = p2[0] + p2[1] + p2[2] + p2[3];
        float m = a / 128.f;
        mv[0] = m;
        mv[1] = rsqrtf(c / 128.f - m * m + 1e-5f);
    }
    __syncthreads();
    x[(size_t)n * FF + t] = (v - mv[0]) * mv[1] * gam[t] + bet[t];
}

__global__ void __launch_bounds__(256) edge_prep(const float* __restrict__ r,
                                                 __half* __restrict__ rbf,
                                                 float* __restrict__ unit) {
    int e = blockIdx.x * 256 + threadIdx.x;
    if (e >= NE) return;
    float x = __ldg(r + 3 * e), y = __ldg(r + 3 * e + 1), z = __ldg(r + 3 * e + 2);
    float d = sqrtf(x * x + y * y + z * z + 3e-15f);
    float inv = 1.f / d;
    unit[3 * e] = x * inv; unit[3 * e + 1] = y * inv; unit[3 * e + 2] = z * inv;
    const float width = 5.0f / 49.0f;
    const float gam = 0.5f / (width * width);
    __half2 buf[32];
    #pragma unroll
    for (int k2 = 0; k2 < 32; k2++) {
        int k0 = k2 * 2, k1 = k2 * 2 + 1;
        float d0 = d - (float)k0 * width;
        float d1 = d - (float)k1 * width;
        float v0 = (k0 < NRBF) ? __expf(-gam * d0 * d0) : 0.f;
        float v1 = (k1 < NRBF) ? __expf(-gam * d1 * d1) : 0.f;
        buf[k2] = __floats2half2_rn(v0, v1);
    }
    uint4* dst = (uint4*)(rbf + (size_t)e * RBFP);
    const uint4* src = (const uint4*)buf;
    #pragma unroll
    for (int q = 0; q < 8; q++) dst[q] = src[q];
}

// ================= qkv: fused 3-way f32x2 SGEMM =================
__global__ void __launch_bounds__(256, 2)
qkv_gemm(const float* __restrict__ Xin,
         const float* __restrict__ Wq, const float* __restrict__ Wk,
         const float* __restrict__ Wv,
         const float* __restrict__ bq, const float* __restrict__ bk,
         const float* __restrict__ bv,
         float* __restrict__ qkvout) {
    const int M = NN, N = 512, K = 128, lda = 128, ldc = 1536;
    int which = blockIdx.x >> 2;
    const float* B    = (which == 0) ? Wq : ((which == 1) ? Wk : Wv);
    const float* bias = (which == 0) ? bq : ((which == 1) ? bk : bv);
    float* C = qkvout + which * 512;
    int col0 = (blockIdx.x & 3) * 128;
    int row0 = blockIdx.y * 128;

    __shared__ float As[2][8][128];
    __shared__ float Bs[2][8][128];

    int t  = threadIdx.x;
    int ty = t >> 4, tx = t & 15;

    int arow = t >> 1;
    int acol = (t & 1) * 4;
    int am   = min(row0 + arow, M - 1);
    const float* Aptr = Xin + (size_t)am * lda + acol;

    int bk_ = t >> 5;
    int bn  = (t & 31) * 4;

    float4 ar, br;
    ar = *(const float4*)(Aptr);
    br = *(const float4*)(B + (size_t)bk_ * N + col0 + bn);

    As[0][acol + 0][arow] = ar.x;
    As[0][acol + 1][arow] = ar.y;
    As[0][acol + 2][arow] = ar.z;
    As[0][acol + 3][arow] = ar.w;
    *(float4*)&Bs[0][bk_][bn] = br;
    __syncthreads();

    ull acc[8][4];
    #pragma unroll
    for (int i = 0; i < 8; i++)
        #pragma unroll
        for (int j = 0; j < 4; j++) acc[i][j] = 0ULL;

    const int nstage = K >> 3;
    for (int s = 0; s < nstage; s++) {
        int cur = s & 1, nxt = cur ^ 1;
        bool more = (s + 1 < nstage);
        if (more) {
            int kk = (s + 1) << 3;
            ar = *(const float4*)(Aptr + kk);
            br = *(const float4*)(B + (size_t)(kk + bk_) * N + col0 + bn);
        }
        #pragma unroll
        for (int k = 0; k < 8; k++) {
            float4 a0 = *(float4*)&As[cur][k][ty * 8];
            float4 a1 = *(float4*)&As[cur][k][ty * 8 + 4];
            ulonglong2 b0 = *(ulonglong2*)&Bs[cur][k][tx * 8];
            ulonglong2 b1 = *(ulonglong2*)&Bs[cur][k][tx * 8 + 4];
            ull a2[8];
            PACK2(a2[0], a0.x); PACK2(a2[1], a0.y);
            PACK2(a2[2], a0.z); PACK2(a2[3], a0.w);
            PACK2(a2[4], a1.x); PACK2(a2[5], a1.y);
            PACK2(a2[6], a1.z); PACK2(a2[7], a1.w);
            #pragma unroll
            for (int i = 0; i < 8; i++) {
                FMA2(acc[i][0], a2[i], b0.x);
                FMA2(acc[i][1], a2[i], b0.y);
                FMA2(acc[i][2], a2[i], b1.x);
                FMA2(acc[i][3], a2[i], b1.y);
            }
        }
        if (more) {
            As[nxt][acol + 0][arow] = ar.x;
            As[nxt][acol + 1][arow] = ar.y;
            As[nxt][acol + 2][arow] = ar.z;
            As[nxt][acol + 3][arow] = ar.w;
            *(float4*)&Bs[nxt][bk_][bn] = br;
        }
        __syncthreads();
    }

    int colb = col0 + tx * 8;
    float4 bs0 = *(const float4*)(bias + colb);
    float4 bs1 = *(const float4*)(bias + colb + 4);
    #pragma unroll
    for (int i = 0; i < 8; i++) {
        int row = row0 + ty * 8 + i;
        if (row >= M) continue;
        float v[8];
        UNPACK2(v[0], v[1], acc[i][0]);
        UNPACK2(v[2], v[3], acc[i][1]);
        UNPACK2(v[4], v[5], acc[i][2]);
        UNPACK2(v[6], v[7], acc[i][3]);
        v[0] += bs0.x; v[1] += bs0.y; v[2] += bs0.z; v[3] += bs0.w;
        v[4] += bs1.x; v[5] += bs1.y; v[6] += bs1.z; v[7] += bs1.w;
        float* cp = C + (size_t)row * ldc + colb;
        *(float4*)cp       = make_float4(v[0], v[1], v[2], v[3]);
        *(float4*)(cp + 4) = make_float4(v[4], v[5], v[6], v[7]);
    }
}

// ================= attn + msg: warp-per-edge =================
__global__ void __launch_bounds__(256) attn_msg(const float* __restrict__ qkv,
                                                const __half* __restrict__ dkdv,
                                                const int* __restrict__ nbrs,
                                                __half* __restrict__ msg) {
    int e = blockIdx.x * 8 + (threadIdx.x >> 5);
    if (e >= NE) return;
    int l = threadIdx.x & 31;
    int i = __ldg(nbrs + 2 * e), j = __ldg(nbrs + 2 * e + 1);
    const float4* q4 = (const float4*)(qkv + (size_t)i * 1536);
    const float4* k4 = (const float4*)(qkv + (size_t)j * 1536 + 512);
    const float4* v4 = (const float4*)(qkv + (size_t)j * 1536 + 1024);
    const uint2* dk2 = (const uint2*)(dkdv + (size_t)e * 1024);
    const uint2* dv2 = dk2 + 128;

    float4 qv[4], kv[4], vv[4];
    uint2 dkv[4], dvv[4];
    #pragma unroll
    for (int h = 0; h < 4; h++) {
        int idx = h * 32 + l;
        qv[h] = q4[idx]; kv[h] = k4[idx]; vv[h] = v4[idx];
        dkv[h] = dk2[idx]; dvv[h] = dv2[idx];
    }
    float p[4];
    #pragma unroll
    for (int h = 0; h < 4; h++) {
        float2 f0 = __half22float2(*(__half2*)&dkv[h].x);
        float2 f1 = __half22float2(*(__half2*)&dkv[h].y);
        p[h] = qv[h].x * kv[h].x * f0.x + qv[h].y * kv[h].y * f0.y
             + qv[h].z * kv[h].z * f1.x + qv[h].w * kv[h].w * f1.y;
    }
    #pragma unroll
    for (int o = 16; o; o >>= 1)
        #pragma unroll
        for (int h = 0; h < 4; h++) p[h] += __shfl_xor_sync(0xffffffffu, p[h], o);

    __half* mrow = msg + (size_t)e * 512;
    #pragma unroll
    for (int h = 0; h < 4; h++) {
        float at = silu_f(p[h]);
        float2 g0 = __half22float2(*(__half2*)&dvv[h].x);
        float2 g1 = __half22float2(*(__half2*)&dvv[h].y);
        __half2 m0 = __floats2half2_rn(vv[h].x * g0.x * at, vv[h].y * g0.y * at);
        __half2 m1 = __floats2half2_rn(vv[h].z * g1.x * at, vv[h].w * g1.y * at);
        uint2 o2;
        o2.x = *(uint32_t*)&m0;
        o2.y = *(uint32_t*)&m1;
        *(uint2*)(mrow + h * 128 + l * 4) = o2;
    }
}

// ================= fp16 mma GEMM =================
// MODE 1: big GEMM (A=msg, B=Wd, NSLICE=3) + scalar-atomic scatter.
// MODE 2: dk/dv fused (A=rbf, slice0=Wdk, slice1=Wdv), silu store to C.
#define SROWU 20
#define ABUFU (128 * SROWU)

template <int MODE, int NSLICE>
__global__ void __launch_bounds__(256)
mma_fp16(const __half* __restrict__ A, const float* __restrict__ B,
         const float* __restrict__ B2,
         const float* __restrict__ bias, const float* __restrict__ bias2,
         __half* __restrict__ C,
         const float* __restrict__ unit, const float* __restrict__ v_j,
         const int* __restrict__ nbrs, float* __restrict__ ds,
         float* __restrict__ dvout,
         int M, int Nld, int Kb, int lda, int nstage) {
    extern __shared__ uint32_t sm[];
    uint32_t* Bbuf = sm + 2 * ABUFU;
    const uint32_t sA = smem_u32(sm);

    const int tid = threadIdx.x;
    const int wid = tid >> 5, lid = tid & 31;
    const int gq = lid >> 2, tig = lid & 3;
    const int wM = wid >> 1, wN = wid & 1;
    const int row0 = (MODE == 1 ? blockIdx.x : blockIdx.y) * 128;
    const int n0s  = (MODE == 1 ? 0 : blockIdx.x * 128);

    float acc[NSLICE][2][8][4];
    #pragma unroll
    for (int s = 0; s < NSLICE; s++)
        #pragma unroll
        for (int a = 0; a < 2; a++)
            #pragma unroll
            for (int b = 0; b < 8; b++)
                #pragma unroll
                for (int c = 0; c < 4; c++) acc[s][a][b][c] = 0.f;

    const int arow = tid >> 1, ac2 = (tid & 1) * 2;
    const int bp = tid & 15, bng = tid >> 4;
    const int bpp = (bp & 3) * 4 + (bp >> 2);
    const __half* aRow = A + (size_t)min(row0 + arow, M - 1) * lda;

    // ldmatrix address (per mf): quadrant layout m8n8.x4 -> {a0,a1,a2,a3}
    const int lq = lid >> 3, lr = lid & 7;
    // row within tile for this lane, col in u32
    const int lrow_base = wM * 32 + (lq & 1) * 8 + lr;
    const int lcol = (lq >> 1) * 4;

    auto stage_A = [&](int s, int buf) {
        const __half* src = aRow + s * 32 + ac2 * 8;
        uint32_t dst = sA + (buf * ABUFU + arow * SROWU + ac2 * 4) * 4;
        CP_ASYNC16(dst, src);
        CP_ASYNC16(dst + 16, src + 8);
    };

    auto stage_B = [&](int s, int buf) {
        int k0g = s * 32 + 2 * bp;
        bool ok0 = (k0g < Kb), ok1 = (k0g + 1 < Kb);
        #pragma unroll
        for (int sl = 0; sl < NSLICE; sl++) {
            const float* Bp = (MODE == 2 && sl == 1) ? B2 : B;
            uint32_t* bb = Bbuf + (sl * 2 + buf) * ABUFU;
            int nbase = (MODE == 1 ? sl * 128 : n0s) + bng * 8;
            #pragma unroll
            for (int h = 0; h < 2; h++) {
                int n4 = nbase + h * 4;
                float4 lo = ok0 ? *(const float4*)(Bp + (size_t)k0g * Nld + n4)
                                : make_float4(0.f, 0.f, 0.f, 0.f);
                float4 hi = ok1 ? *(const float4*)(Bp + (size_t)(k0g + 1) * Nld + n4)
                                : make_float4(0.f, 0.f, 0.f, 0.f);
                __half2 h0 = __floats2half2_rn(lo.x, hi.x);
                __half2 h1 = __floats2half2_rn(lo.y, hi.y);
                __half2 h2 = __floats2half2_rn(lo.z, hi.z);
                __half2 h3 = __floats2half2_rn(lo.w, hi.w);
                int nr = bng * 8 + h * 4;
                bb[(nr + 0) * SROWU + bpp] = *(uint32_t*)&h0;
                bb[(nr + 1) * SROWU + bpp] = *(uint32_t*)&h1;
                bb[(nr + 2) * SROWU + bpp] = *(uint32_t*)&h2;
                bb[(nr + 3) * SROWU + bpp] = *(uint32_t*)&h3;
            }
        }
    };

    stage_A(0, 0);
    CP_COMMIT();
    stage_B(0, 0);
    CP_WAIT0();
    __syncthreads();

    for (int s = 0; s < nstage; s++) {
        int cur = s & 1;
        bool more = (s + 1 < nstage);
        if (more) {
            stage_A(s + 1, cur ^ 1);
            CP_COMMIT();
            stage_B(s + 1, cur ^ 1);
        }

        uint32_t af[2][2][4];
        #pragma unroll
        for (int mf = 0; mf < 2; mf++) {
            uint32_t base = sA + (cur * ABUFU + (lrow_base + mf * 16) * SROWU + lcol) * 4;
            LDSM_X4(af[mf][0][0], af[mf][0][1], af[mf][0][2], af[mf][0][3], base);
            LDSM_X4(af[mf][1][0], af[mf][1][1], af[mf][1][2], af[mf][1][3], base + 32);
        }
        const uint32_t* Bbase = sm + 2 * ABUFU + cur * ABUFU;
        #pragma unroll
        for (int sl = 0; sl < NSLICE; sl++) {
            const uint32_t* Bb = Bbase + sl * 2 * ABUFU;
            #pragma unroll
            for (int nf = 0; nf < 8; nf++) {
                int n = wN * 64 + nf * 8 + gq;
                uint4 bv = *(const uint4*)(Bb + n * SROWU + tig * 4);
                MMA_F16(acc[sl][0][nf], af[0][0][0], af[0][0][1], af[0][0][2], af[0][0][3], bv.x, bv.y);
                MMA_F16(acc[sl][1][nf], af[1][0][0], af[1][0][1], af[1][0][2], af[1][0][3], bv.x, bv.y);
                MMA_F16(acc[sl][0][nf], af[0][1][0], af[0][1][1], af[0][1][2], af[0][1][3], bv.z, bv.w);
                MMA_F16(acc[sl][1][nf], af[1][1][0], af[1][1][1], af[1][1][2], af[1][1][3], bv.z, bv.w);
            }
        }
        if (more) CP_WAIT0();
        __syncthreads();
    }

    if constexpr (MODE == 2) {
        #pragma unroll
        for (int mf = 0; mf < 2; mf++)
        #pragma unroll
        for (int rs = 0; rs < 2; rs++) {
            int r = row0 + wM * 32 + mf * 16 + rs * 8 + gq;
            if (r >= M) continue;
            #pragma unroll
            for (int sl = 0; sl < NSLICE; sl++) {
                const float* bp2 = sl ? bias2 : bias;
                #pragma unroll
                for (int nf = 0; nf < 8; nf++) {
                    int nc = wN * 64 + nf * 8 + tig * 2;
                    float v0 = silu_f(acc[sl][mf][nf][rs * 2 + 0] + __ldg(bp2 + n0s + nc));
                    float v1 = silu_f(acc[sl][mf][nf][rs * 2 + 1] + __ldg(bp2 + n0s + nc + 1));
                    *(__half2*)(C + (size_t)r * 1024 + sl * 512 + n0s + nc) =
                        __floats2half2_rn(v0, v1);
                }
            }
        }
    } else {
        #pragma unroll
        for (int mf = 0; mf < 2; mf++)
        #pragma unroll
        for (int rs = 0; rs < 2; rs++) {
            int e = row0 + wM * 32 + mf * 16 + rs * 8 + gq;
            if (e >= M) continue;
            int ii = nbrs[2 * e], jj = nbrs[2 * e + 1];
            float ux = unit[3 * e], uy = unit[3 * e + 1], uz = unit[3 * e + 2];
            #pragma unroll
            for (int nf = 0; nf < 8; nf++) {
                #pragma unroll
                for (int c = 0; c < 2; c++) {
                    int f = wN * 64 + nf * 8 + tig * 2 + c;
                    float s0 = acc[0][mf][nf][rs * 2 + c] + __ldg(bias + f);
                    float s1 = acc[1][mf][nf][rs * 2 + c] + __ldg(bias + 128 + f);
                    float s2 = acc[2][mf][nf][rs * 2 + c] + __ldg(bias + 256 + f);
                    atomicAdd(ds + (size_t)ii * FF + f, s1);
                    const float* vj = v_j + ((size_t)jj * FF + f) * 3;
                    float* dv = dvout + ((size_t)ii * FF + f) * 3;
                    atomicAdd(dv + 0, s2 * ux + s0 * vj[0]);
                    atomicAdd(dv + 1, s2 * uy + s0 * vj[1]);
                    atomicAdd(dv + 2, s2 * uz + s0 * vj[2]);
                }
            }
        }
    }
}

// ================= launch =================
extern "C" void kernel_launch(void* const* d_in, const int* in_sizes, int n_in,
                              void* d_out, int out_size) {
    const float* s_j  = (const float*)d_in[0];
    const float* v_j  = (const float*)d_in[1];
    const float* r_ij = (const float*)d_in[2];
    const int*   nbrs = (const int*)  d_in[3];
    const float* ln_g = (const float*)d_in[4];
    const float* ln_b = (const float*)d_in[5];
    const float* Wq   = (const float*)d_in[6];
    const float* bq   = (const float*)d_in[7];
    const float* Wk   = (const float*)d_in[8];
    const float* bk   = (const float*)d_in[9];
    const float* Wv   = (const float*)d_in[10];
    const float* bv   = (const float*)d_in[11];
    const float* Wdk  = (const float*)d_in[12];
    const float* bdk  = (const float*)d_in[13];
    const float* Wdv  = (const float*)d_in[14];
    const float* bdv  = (const float*)d_in[15];
    const float* Wd   = (const float*)d_in[16];
    const float* bd   = (const float*)d_in[17];
    float* out = (float*)d_out;

    float *x, *qkv, *unit;
    __half *rbf, *dkdv, *msg;
    cudaGetSymbolAddress((void**)&x,    g_x);
    cudaGetSymbolAddress((void**)&qkv,  g_qkv);
    cudaGetSymbolAddress((void**)&rbf,  g_rbf);
    cudaGetSymbolAddress((void**)&unit, g_unit);
    cudaGetSymbolAddress((void**)&dkdv, g_dkdv);
    cudaGetSymbolAddress((void**)&msg,  g_msg);

    const int SMEM_DKDV = (2 + 2 * 2) * ABUFU * 4;   // 61440
    const int SMEM_BIG  = (2 + 3 * 2) * ABUFU * 4;   // 81920
    cudaFuncSetAttribute(mma_fp16<2, 2>, cudaFuncAttributeMaxDynamicSharedMemorySize, SMEM_DKDV);
    cudaFuncSetAttribute(mma_fp16<1, 3>, cudaFuncAttributeMaxDynamicSharedMemorySize, SMEM_BIG);

    const int OUT_ELEMS = NN * FF * 4;
    zero_kernel<<<(OUT_ELEMS + 255) / 256, 256>>>(out, OUT_ELEMS);

    ln_kernel<<<NN, 128>>>(s_j, ln_g, ln_b, x);

    dim3 gq3(12, (NN + 127) / 128);
    qkv_gemm<<<gq3, 256>>>(x, Wq, Wk, Wv, bq, bk, bv, qkv);

    edge_prep<<<(NE + 255) / 256, 256>>>(r_ij, rbf, unit);

    int mtiles = (NE + 127) / 128;   // 1954
    dim3 ge(4, mtiles);
    mma_fp16<2, 2><<<ge, 256, SMEM_DKDV>>>(rbf, Wdk, Wdv, bdk, bdv, dkdv,
                                           nullptr, nullptr, nullptr, nullptr, nullptr,
                                           NE, 512, 50, RBFP, 2);

    attn_msg<<<(NE + 7) / 8, 256>>>(qkv, dkdv, nbrs, msg);

    mma_fp16<1, 3><<<mtiles, 256, SMEM_BIG>>>(msg, Wd, nullptr, bd, nullptr, nullptr,
                                              unit, v_j, nbrs, out, out + NN * FF,
                                              NE, 384, 512, 512, 16);
}

// round 9
// speedup vs baseline: 1.5165x; 1.5165x over previous
#include <cuda_runtime.h>
#include <cuda_fp16.h>
#include <math.h>
#include <stdint.h>

#define NN   10000
#define NE   250000
#define FF   128
#define NRBF 50
#define RBFP 64

typedef unsigned long long ull;

// ---------------- scratch ----------------
__device__ float  g_x[NN * FF];
__device__ float  g_qkv[NN * 3 * 512];
__device__ __half g_rbf[(size_t)NE * RBFP];
__device__ float  g_unit[(size_t)NE * 3];
__device__ __half g_dkdv[(size_t)NE * 1024];
__device__ __half g_msg[(size_t)NE * 512];
// pre-permuted half B matrices: [(n*nstage + s)*16 + p] u32
__device__ uint32_t g_wdp[384 * 16 * 16];    // Wd:  K=512 (16 stages), N=384
__device__ uint32_t g_wdkp[512 * 2 * 16];    // Wdk: K=50->64 (2 stages), N=512
__device__ uint32_t g_wdvp[512 * 2 * 16];    // Wdv

#define FMA2(acc, a, b) asm("fma.rn.f32x2 %0, %1, %2, %0;" : "+l"(acc) : "l"(a), "l"(b))
#define PACK2(dst, f)   asm("mov.b64 %0, {%1, %1};" : "=l"(dst) : "f"(f))
#define UNPACK2(lo, hi, v) asm("mov.b64 {%0, %1}, %2;" : "=f"(lo), "=f"(hi) : "l"(v))

__device__ __forceinline__ uint32_t smem_u32(const void* p) {
    uint32_t a;
    asm("{ .reg .u64 t; cvta.to.shared.u64 t, %1; cvt.u32.u64 %0, t; }" : "=r"(a) : "l"(p));
    return a;
}
__device__ __forceinline__ float silu_f(float v) {
    return v / (1.f + __expf(-v));
}

#define MMA_F16(c, a0, a1, a2, a3, b0, b1)                                \
    asm volatile("mma.sync.aligned.m16n8k16.row.col.f32.f16.f16.f32 "     \
        "{%0,%1,%2,%3}, {%4,%5,%6,%7}, {%8,%9}, {%0,%1,%2,%3};"           \
        : "+f"((c)[0]), "+f"((c)[1]), "+f"((c)[2]), "+f"((c)[3])          \
        : "r"(a0), "r"(a1), "r"(a2), "r"(a3), "r"(b0), "r"(b1))

#define CP_ASYNC16(dst, src) \
    asm volatile("cp.async.ca.shared.global [%0], [%1], 16;" :: "r"(dst), "l"(src))
#define CP_COMMIT() asm volatile("cp.async.commit_group;" ::: "memory")
#define CP_WAIT0()  asm volatile("cp.async.wait_group 0;" ::: "memory")

// ================= small kernels =================
__global__ void zero_kernel(float* __restrict__ p, int n) {
    int i = blockIdx.x * blockDim.x + threadIdx.x;
    if (i < n) p[i] = 0.f;
}

// Convert W[K x Nld] float -> n-major, stage-blocked, fragment-permuted half pairs.
// out[(n*nst + s)*16 + p] = half2(W[k][n], W[k+1][n]), k = s*32 + bp*2,
// bp = (p&3)*4 + (p>>2)  (self-inverse permutation used by the smem B layout).
__global__ void conv_B(const float* __restrict__ W, uint32_t* __restrict__ out,
                       int N, int nst, int Kreal, int Nld) {
    int i = blockIdx.x * 256 + threadIdx.x;
    int total = N * nst * 16;
    if (i >= total) return;
    int n = i / (nst * 16);
    int rem = i % (nst * 16);
    int s = rem >> 4, p = rem & 15;
    int bp = (p & 3) * 4 + (p >> 2);
    int k = s * 32 + bp * 2;
    float lo = (k < Kreal)     ? W[(size_t)k * Nld + n]       : 0.f;
    float hi = (k + 1 < Kreal) ? W[(size_t)(k + 1) * Nld + n] : 0.f;
    __half2 h = __floats2half2_rn(lo, hi);
    out[i] = *(uint32_t*)&h;
}

__global__ void __launch_bounds__(128) ln_kernel(const float* __restrict__ s,
                                                 const float* __restrict__ gam,
                                                 const float* __restrict__ bet,
                                                 float* __restrict__ x) {
    int n = blockIdx.x, t = threadIdx.x;
    float v = s[(size_t)n * FF + t];
    float s1 = v, s2 = v * v;
    #pragma unroll
    for (int o = 16; o; o >>= 1) {
        s1 += __shfl_down_sync(0xffffffffu, s1, o);
        s2 += __shfl_down_sync(0xffffffffu, s2, o);
    }
    __shared__ float p1[4], p2[4], mv[2];
    if ((t & 31) == 0) { p1[t >> 5] = s1; p2[t >> 5] = s2; }
    __syncthreads();
    if (t == 0) {
        float a = p1[0] + p1[1] + p1[2] + p1[3];
        float c = p2[0] + p2[1] + p2[2] + p2[3];
        float m = a / 128.f;
        mv[0] = m;
        mv[1] = rsqrtf(c / 128.f - m * m + 1e-5f);
    }
    __syncthreads();
    x[(size_t)n * FF + t] = (v - mv[0]) * mv[1] * gam[t] + bet[t];
}

__global__ void __launch_bounds__(256) edge_prep(const float* __restrict__ r,
                                                 __half* __restrict__ rbf,
                                                 float* __restrict__ unit) {
    int e = blockIdx.x * 256 + threadIdx.x;
    if (e >= NE) return;
    float x = __ldg(r + 3 * e), y = __ldg(r + 3 * e + 1), z = __ldg(r + 3 * e + 2);
    float d = sqrtf(x * x + y * y + z * z + 3e-15f);
    float inv = 1.f / d;
    unit[3 * e] = x * inv; unit[3 * e + 1] = y * inv; unit[3 * e + 2] = z * inv;
    const float width = 5.0f / 49.0f;
    const float gam = 0.5f / (width * width);
    __half2 buf[32];
    #pragma unroll
    for (int k2 = 0; k2 < 32; k2++) {
        int k0 = k2 * 2, k1 = k2 * 2 + 1;
        float d0 = d - (float)k0 * width;
        float d1 = d - (float)k1 * width;
        float v0 = (k0 < NRBF) ? __expf(-gam * d0 * d0) : 0.f;
        float v1 = (k1 < NRBF) ? __expf(-gam * d1 * d1) : 0.f;
        buf[k2] = __floats2half2_rn(v0, v1);
    }
    uint4* dst = (uint4*)(rbf + (size_t)e * RBFP);
    const uint4* src = (const uint4*)buf;
    #pragma unroll
    for (int q = 0; q < 8; q++) dst[q] = src[q];
}

// ================= qkv: fused 3-way f32x2 SGEMM =================
__global__ void __launch_bounds__(256, 2)
qkv_gemm(const float* __restrict__ Xin,
         const float* __restrict__ Wq, const float* __restrict__ Wk,
         const float* __restrict__ Wv,
         const float* __restrict__ bq, const float* __restrict__ bk,
         const float* __restrict__ bv,
         float* __restrict__ qkvout) {
    const int M = NN, N = 512, K = 128, lda = 128, ldc = 1536;
    int which = blockIdx.x >> 2;
    const float* B    = (which == 0) ? Wq : ((which == 1) ? Wk : Wv);
    const float* bias = (which == 0) ? bq : ((which == 1) ? bk : bv);
    float* C = qkvout + which * 512;
    int col0 = (blockIdx.x & 3) * 128;
    int row0 = blockIdx.y * 128;

    __shared__ float As[2][8][128];
    __shared__ float Bs[2][8][128];

    int t  = threadIdx.x;
    int ty = t >> 4, tx = t & 15;

    int arow = t >> 1;
    int acol = (t & 1) * 4;
    int am   = min(row0 + arow, M - 1);
    const float* Aptr = Xin + (size_t)am * lda + acol;

    int bk_ = t >> 5;
    int bn  = (t & 31) * 4;

    float4 ar, br;
    ar = *(const float4*)(Aptr);
    br = *(const float4*)(B + (size_t)bk_ * N + col0 + bn);

    As[0][acol + 0][arow] = ar.x;
    As[0][acol + 1][arow] = ar.y;
    As[0][acol + 2][arow] = ar.z;
    As[0][acol + 3][arow] = ar.w;
    *(float4*)&Bs[0][bk_][bn] = br;
    __syncthreads();

    ull acc[8][4];
    #pragma unroll
    for (int i = 0; i < 8; i++)
        #pragma unroll
        for (int j = 0; j < 4; j++) acc[i][j] = 0ULL;

    const int nstage = K >> 3;
    for (int s = 0; s < nstage; s++) {
        int cur = s & 1, nxt = cur ^ 1;
        bool more = (s + 1 < nstage);
        if (more) {
            int kk = (s + 1) << 3;
            ar = *(const float4*)(Aptr + kk);
            br = *(const float4*)(B + (size_t)(kk + bk_) * N + col0 + bn);
        }
        #pragma unroll
        for (int k = 0; k < 8; k++) {
            float4 a0 = *(float4*)&As[cur][k][ty * 8];
            float4 a1 = *(float4*)&As[cur][k][ty * 8 + 4];
            ulonglong2 b0 = *(ulonglong2*)&Bs[cur][k][tx * 8];
            ulonglong2 b1 = *(ulonglong2*)&Bs[cur][k][tx * 8 + 4];
            ull a2[8];
            PACK2(a2[0], a0.x); PACK2(a2[1], a0.y);
            PACK2(a2[2], a0.z); PACK2(a2[3], a0.w);
            PACK2(a2[4], a1.x); PACK2(a2[5], a1.y);
            PACK2(a2[6], a1.z); PACK2(a2[7], a1.w);
            #pragma unroll
            for (int i = 0; i < 8; i++) {
                FMA2(acc[i][0], a2[i], b0.x);
                FMA2(acc[i][1], a2[i], b0.y);
                FMA2(acc[i][2], a2[i], b1.x);
                FMA2(acc[i][3], a2[i], b1.y);
            }
        }
        if (more) {
            As[nxt][acol + 0][arow] = ar.x;
            As[nxt][acol + 1][arow] = ar.y;
            As[nxt][acol + 2][arow] = ar.z;
            As[nxt][acol + 3][arow] = ar.w;
            *(float4*)&Bs[nxt][bk_][bn] = br;
        }
        __syncthreads();
    }

    int colb = col0 + tx * 8;
    float4 bs0 = *(const float4*)(bias + colb);
    float4 bs1 = *(const float4*)(bias + colb + 4);
    #pragma unroll
    for (int i = 0; i < 8; i++) {
        int row = row0 + ty * 8 + i;
        if (row >= M) continue;
        float v[8];
        UNPACK2(v[0], v[1], acc[i][0]);
        UNPACK2(v[2], v[3], acc[i][1]);
        UNPACK2(v[4], v[5], acc[i][2]);
        UNPACK2(v[6], v[7], acc[i][3]);
        v[0] += bs0.x; v[1] += bs0.y; v[2] += bs0.z; v[3] += bs0.w;
        v[4] += bs1.x; v[5] += bs1.y; v[6] += bs1.z; v[7] += bs1.w;
        float* cp = C + (size_t)row * ldc + colb;
        *(float4*)cp       = make_float4(v[0], v[1], v[2], v[3]);
        *(float4*)(cp + 4) = make_float4(v[4], v[5], v[6], v[7]);
    }
}

// ================= attn + msg: warp-per-edge =================
__global__ void __launch_bounds__(256) attn_msg(const float* __restrict__ qkv,
                                                const __half* __restrict__ dkdv,
                                                const int* __restrict__ nbrs,
                                                __half* __restrict__ msg) {
    int e = blockIdx.x * 8 + (threadIdx.x >> 5);
    if (e >= NE) return;
    int l = threadIdx.x & 31;
    int i = __ldg(nbrs + 2 * e), j = __ldg(nbrs + 2 * e + 1);
    const float4* q4 = (const float4*)(qkv + (size_t)i * 1536);
    const float4* k4 = (const float4*)(qkv + (size_t)j * 1536 + 512);
    const float4* v4 = (const float4*)(qkv + (size_t)j * 1536 + 1024);
    const uint2* dk2 = (const uint2*)(dkdv + (size_t)e * 1024);
    const uint2* dv2 = dk2 + 128;

    float4 qv[4], kv[4], vv[4];
    uint2 dkv[4], dvv[4];
    #pragma unroll
    for (int h = 0; h < 4; h++) {
        int idx = h * 32 + l;
        qv[h] = q4[idx]; kv[h] = k4[idx]; vv[h] = v4[idx];
        dkv[h] = dk2[idx]; dvv[h] = dv2[idx];
    }
    float p[4];
    #pragma unroll
    for (int h = 0; h < 4; h++) {
        float2 f0 = __half22float2(*(__half2*)&dkv[h].x);
        float2 f1 = __half22float2(*(__half2*)&dkv[h].y);
        p[h] = qv[h].x * kv[h].x * f0.x + qv[h].y * kv[h].y * f0.y
             + qv[h].z * kv[h].z * f1.x + qv[h].w * kv[h].w * f1.y;
    }
    #pragma unroll
    for (int o = 16; o; o >>= 1)
        #pragma unroll
        for (int h = 0; h < 4; h++) p[h] += __shfl_xor_sync(0xffffffffu, p[h], o);

    __half* mrow = msg + (size_t)e * 512;
    #pragma unroll
    for (int h = 0; h < 4; h++) {
        float at = silu_f(p[h]);
        float2 g0 = __half22float2(*(__half2*)&dvv[h].x);
        float2 g1 = __half22float2(*(__half2*)&dvv[h].y);
        __half2 m0 = __floats2half2_rn(vv[h].x * g0.x * at, vv[h].y * g0.y * at);
        __half2 m1 = __floats2half2_rn(vv[h].z * g1.x * at, vv[h].w * g1.y * at);
        uint2 o2;
        o2.x = *(uint32_t*)&m0;
        o2.y = *(uint32_t*)&m1;
        *(uint2*)(mrow + h * 128 + l * 4) = o2;
    }
}

// ================= fp16 mma GEMM =================
// EPI=0 (dk or dv): silu + store at C[r*ldc + n0s + nc]; B from pre-permuted Bp.
// EPI=1 (big): NSLICE=3 (full N=384 in one CTA) + scalar-atomic fused scatter.
#define SROWU 20
#define ABUFU (128 * SROWU)

template <int EPI, int NSLICE>
__global__ void __launch_bounds__(256)
mma_fp16(const __half* __restrict__ A, const uint32_t* __restrict__ Bp,
         const float* __restrict__ bias, __half* __restrict__ C, int ldc,
         const float* __restrict__ unit, const float* __restrict__ v_j,
         const int* __restrict__ nbrs, float* __restrict__ ds,
         float* __restrict__ dvout,
         int M, int lda, int nstage) {
    extern __shared__ uint32_t sm[];
    const uint32_t sA = smem_u32(sm);
    const uint32_t sB0 = sA + 2 * ABUFU * 4;

    const int tid = threadIdx.x;
    const int wid = tid >> 5, lid = tid & 31;
    const int gq = lid >> 2, tig = lid & 3;
    const int wM = wid >> 1, wN = wid & 1;
    const int row0 = (EPI == 1 ? blockIdx.x : blockIdx.y) * 128;
    const int n0s  = (EPI == 1 ? 0 : blockIdx.x * 128);

    float acc[NSLICE][2][8][4];
    #pragma unroll
    for (int s = 0; s < NSLICE; s++)
        #pragma unroll
        for (int a = 0; a < 2; a++)
            #pragma unroll
            for (int b = 0; b < 8; b++)
                #pragma unroll
                for (int c = 0; c < 4; c++) acc[s][a][b][c] = 0.f;

    const int arow = tid >> 1, ac2 = (tid & 1) * 2;
    const __half* aRow = A + (size_t)min(row0 + arow, M - 1) * lda;

    auto stage_A = [&](int s, int buf) {
        const __half* src = aRow + s * 32 + ac2 * 8;
        uint32_t dst = sA + (buf * ABUFU + arow * SROWU + ac2 * 4) * 4;
        CP_ASYNC16(dst, src);
        CP_ASYNC16(dst + 16, src + 8);
    };

    // B staging: pure cp.async from the pre-permuted gmem layout.
    // NSLICE*512 chunks of 16B per stage; chunk c of slice sl:
    //   n = c>>2, q = c&3; src = Bp[((ng*nstage + s)*16 + q*4)]
    auto stage_B = [&](int s, int buf) {
        #pragma unroll
        for (int i = 0; i < NSLICE * 2; i++) {
            int cid = tid + i * 256;
            int sl = cid >> 9;
            int c  = cid & 511;
            int n = c >> 2, q = c & 3;
            int ng = (EPI == 1 ? sl * 128 : n0s) + n;
            const uint32_t* src = Bp + ((size_t)ng * nstage + s) * 16 + q * 4;
            uint32_t dst = sB0 + ((sl * 2 + buf) * ABUFU + n * SROWU + q * 4) * 4;
            CP_ASYNC16(dst, src);
        }
    };

    stage_A(0, 0);
    stage_B(0, 0);
    CP_COMMIT();
    CP_WAIT0();
    __syncthreads();

    for (int s = 0; s < nstage; s++) {
        int cur = s & 1;
        bool more = (s + 1 < nstage);
        if (more) {
            stage_A(s + 1, cur ^ 1);
            stage_B(s + 1, cur ^ 1);
            CP_COMMIT();
        }

        uint32_t af[2][2][4];
        const uint32_t* Ab = sm + cur * ABUFU;
        #pragma unroll
        for (int mf = 0; mf < 2; mf++) {
            int r0 = wM * 32 + mf * 16 + gq;
            const uint32_t* p0 = Ab + r0 * SROWU;
            const uint32_t* p1 = Ab + (r0 + 8) * SROWU;
            #pragma unroll
            for (int ks = 0; ks < 2; ks++) {
                af[mf][ks][0] = p0[tig + 8 * ks];
                af[mf][ks][1] = p1[tig + 8 * ks];
                af[mf][ks][2] = p0[tig + 4 + 8 * ks];
                af[mf][ks][3] = p1[tig + 4 + 8 * ks];
            }
        }
        const uint32_t* Bbase = sm + 2 * ABUFU + cur * ABUFU;
        #pragma unroll
        for (int sl = 0; sl < NSLICE; sl++) {
            const uint32_t* Bb = Bbase + sl * 2 * ABUFU;
            #pragma unroll
            for (int nf = 0; nf < 8; nf++) {
                int n = wN * 64 + nf * 8 + gq;
                uint4 bv = *(const uint4*)(Bb + n * SROWU + tig * 4);
                MMA_F16(acc[sl][0][nf], af[0][0][0], af[0][0][1], af[0][0][2], af[0][0][3], bv.x, bv.y);
                MMA_F16(acc[sl][1][nf], af[1][0][0], af[1][0][1], af[1][0][2], af[1][0][3], bv.x, bv.y);
                MMA_F16(acc[sl][0][nf], af[0][1][0], af[0][1][1], af[0][1][2], af[0][1][3], bv.z, bv.w);
                MMA_F16(acc[sl][1][nf], af[1][1][0], af[1][1][1], af[1][1][2], af[1][1][3], bv.z, bv.w);
            }
        }
        if (more) CP_WAIT0();
        __syncthreads();
    }

    if constexpr (EPI == 0) {
        #pragma unroll
        for (int mf = 0; mf < 2; mf++)
        #pragma unroll
        for (int rs = 0; rs < 2; rs++) {
            int r = row0 + wM * 32 + mf * 16 + rs * 8 + gq;
            if (r >= M) continue;
            #pragma unroll
            for (int nf = 0; nf < 8; nf++) {
                int nc = wN * 64 + nf * 8 + tig * 2;
                float v0 = silu_f(acc[0][mf][nf][rs * 2 + 0] + __ldg(bias + n0s + nc));
                float v1 = silu_f(acc[0][mf][nf][rs * 2 + 1] + __ldg(bias + n0s + nc + 1));
                *(__half2*)(C + (size_t)r * ldc + n0s + nc) = __floats2half2_rn(v0, v1);
            }
        }
    } else {
        #pragma unroll
        for (int mf = 0; mf < 2; mf++)
        #pragma unroll
        for (int rs = 0; rs < 2; rs++) {
            int e = row0 + wM * 32 + mf * 16 + rs * 8 + gq;
            if (e >= M) continue;
            int ii = nbrs[2 * e], jj = nbrs[2 * e + 1];
            float ux = unit[3 * e], uy = unit[3 * e + 1], uz = unit[3 * e + 2];
            #pragma unroll
            for (int nf = 0; nf < 8; nf++) {
                #pragma unroll
                for (int c = 0; c < 2; c++) {
                    int f = wN * 64 + nf * 8 + tig * 2 + c;
                    float s0 = acc[0][mf][nf][rs * 2 + c] + __ldg(bias + f);
                    float s1 = acc[1][mf][nf][rs * 2 + c] + __ldg(bias + 128 + f);
                    float s2 = acc[2][mf][nf][rs * 2 + c] + __ldg(bias + 256 + f);
                    atomicAdd(ds + (size_t)ii * FF + f, s1);
                    const float* vj = v_j + ((size_t)jj * FF + f) * 3;
                    float* dv = dvout + ((size_t)ii * FF + f) * 3;
                    atomicAdd(dv + 0, s2 * ux + s0 * vj[0]);
                    atomicAdd(dv + 1, s2 * uy + s0 * vj[1]);
                    atomicAdd(dv + 2, s2 * uz + s0 * vj[2]);
                }
            }
        }
    }
}

// ================= launch =================
extern "C" void kernel_launch(void* const* d_in, const int* in_sizes, int n_in,
                              void* d_out, int out_size) {
    const float* s_j  = (const float*)d_in[0];
    const float* v_j  = (const float*)d_in[1];
    const float* r_ij = (const float*)d_in[2];
    const int*   nbrs = (const int*)  d_in[3];
    const float* ln_g = (const float*)d_in[4];
    const float* ln_b = (const float*)d_in[5];
    const float* Wq   = (const float*)d_in[6];
    const float* bq   = (const float*)d_in[7];
    const float* Wk   = (const float*)d_in[8];
    const float* bk   = (const float*)d_in[9];
    const float* Wv   = (const float*)d_in[10];
    const float* bv   = (const float*)d_in[11];
    const float* Wdk  = (const float*)d_in[12];
    const float* bdk  = (const float*)d_in[13];
    const float* Wdv  = (const float*)d_in[14];
    const float* bdv  = (const float*)d_in[15];
    const float* Wd   = (const float*)d_in[16];
    const float* bd   = (const float*)d_in[17];
    float* out = (float*)d_out;

    float *x, *qkv, *unit;
    __half *rbf, *dkdv, *msg;
    uint32_t *wdp, *wdkp, *wdvp;
    cudaGetSymbolAddress((void**)&x,    g_x);
    cudaGetSymbolAddress((void**)&qkv,  g_qkv);
    cudaGetSymbolAddress((void**)&rbf,  g_rbf);
    cudaGetSymbolAddress((void**)&unit, g_unit);
    cudaGetSymbolAddress((void**)&dkdv, g_dkdv);
    cudaGetSymbolAddress((void**)&msg,  g_msg);
    cudaGetSymbolAddress((void**)&wdp,  g_wdp);
    cudaGetSymbolAddress((void**)&wdkp, g_wdkp);
    cudaGetSymbolAddress((void**)&wdvp, g_wdvp);

    const int SMEM_DKDV = (2 + 1 * 2) * ABUFU * 4;   // 40960
    const int SMEM_BIG  = (2 + 3 * 2) * ABUFU * 4;   // 81920
    cudaFuncSetAttribute(mma_fp16<0, 1>, cudaFuncAttributeMaxDynamicSharedMemorySize, SMEM_DKDV);
    cudaFuncSetAttribute(mma_fp16<1, 3>, cudaFuncAttributeMaxDynamicSharedMemorySize, SMEM_BIG);

    const int OUT_ELEMS = NN * FF * 4;
    zero_kernel<<<(OUT_ELEMS + 255) / 256, 256>>>(out, OUT_ELEMS);

    // pre-permute weights to half (tiny)
    conv_B<<<(384 * 16 * 16 + 255) / 256, 256>>>(Wd,  wdp,  384, 16, 512, 384);
    conv_B<<<(512 * 2 * 16 + 255) / 256, 256>>>(Wdk, wdkp, 512, 2, 50, 512);
    conv_B<<<(512 * 2 * 16 + 255) / 256, 256>>>(Wdv, wdvp, 512, 2, 50, 512);

    ln_kernel<<<NN, 128>>>(s_j, ln_g, ln_b, x);

    dim3 gq3(12, (NN + 127) / 128);
    qkv_gemm<<<gq3, 256>>>(x, Wq, Wk, Wv, bq, bk, bv, qkv);

    edge_prep<<<(NE + 255) / 256, 256>>>(r_ij, rbf, unit);

    int mtiles = (NE + 127) / 128;   // 1954
    dim3 ge(4, mtiles);
    mma_fp16<0, 1><<<ge, 256, SMEM_DKDV>>>(rbf, wdkp, bdk, dkdv, 1024,
                                           nullptr, nullptr, nullptr, nullptr, nullptr,
                                           NE, RBFP, 2);
    mma_fp16<0, 1><<<ge, 256, SMEM_DKDV>>>(rbf, wdvp, bdv, dkdv + 512, 1024,
                                           nullptr, nullptr, nullptr, nullptr, nullptr,
                                           NE, RBFP, 2);

    attn_msg<<<(NE + 7) / 8, 256>>>(qkv, dkdv, nbrs, msg);

    mma_fp16<1, 3><<<mtiles, 256, SMEM_BIG>>>(msg, wdp, bd, nullptr, 0,
                                              unit, v_j, nbrs, out, out + NN * FF,
                                              NE, 512, 16);
}

// round 10
// speedup vs baseline: 1.6792x; 1.1073x over previous
#include <cuda_runtime.h>
#include <cuda_fp16.h>
#include <math.h>
#include <stdint.h>

#define NN   10000
#define NE   250000
#define FF   128
#define NRBF 50
#define RBFP 64

typedef unsigned long long ull;

// ---------------- scratch ----------------
__device__ float  g_x[NN * FF];
__device__ float  g_qkv[NN * 3 * 512];
__device__ __half g_rbf[(size_t)NE * RBFP];
__device__ float  g_unit[(size_t)NE * 3];
__device__ __half g_dkdv[(size_t)NE * 1024];
__device__ __half g_msg[(size_t)NE * 512];
__device__ float  g_eout[(size_t)NE * 384];     // per-edge s0|s1|s2 (biased)
__device__ uint32_t g_wdp[384 * 16 * 16];
__device__ uint32_t g_wdkp[512 * 2 * 16];
__device__ uint32_t g_wdvp[512 * 2 * 16];
__device__ int g_cnt[NN];
__device__ int g_off[NN + 1];
__device__ int g_pos[NN];
__device__ int g_eidx[NE];

#define FMA2(acc, a, b) asm("fma.rn.f32x2 %0, %1, %2, %0;" : "+l"(acc) : "l"(a), "l"(b))
#define PACK2(dst, f)   asm("mov.b64 %0, {%1, %1};" : "=l"(dst) : "f"(f))
#define UNPACK2(lo, hi, v) asm("mov.b64 {%0, %1}, %2;" : "=f"(lo), "=f"(hi) : "l"(v))

__device__ __forceinline__ uint32_t smem_u32(const void* p) {
    uint32_t a;
    asm("{ .reg .u64 t; cvta.to.shared.u64 t, %1; cvt.u32.u64 %0, t; }" : "=r"(a) : "l"(p));
    return a;
}
__device__ __forceinline__ float silu_f(float v) {
    return v / (1.f + __expf(-v));
}

#define MMA_F16(c, a0, a1, a2, a3, b0, b1)                                \
    asm volatile("mma.sync.aligned.m16n8k16.row.col.f32.f16.f16.f32 "     \
        "{%0,%1,%2,%3}, {%4,%5,%6,%7}, {%8,%9}, {%0,%1,%2,%3};"           \
        : "+f"((c)[0]), "+f"((c)[1]), "+f"((c)[2]), "+f"((c)[3])          \
        : "r"(a0), "r"(a1), "r"(a2), "r"(a3), "r"(b0), "r"(b1))

#define CP_ASYNC16(dst, src) \
    asm volatile("cp.async.ca.shared.global [%0], [%1], 16;" :: "r"(dst), "l"(src))
#define CP_COMMIT() asm volatile("cp.async.commit_group;" ::: "memory")
#define CP_WAIT0()  asm volatile("cp.async.wait_group 0;" ::: "memory")

// ================= CSR build =================
__global__ void zero_int(int* __restrict__ p, int n) {
    int i = blockIdx.x * blockDim.x + threadIdx.x;
    if (i < n) p[i] = 0;
}
__global__ void csr_hist(const int* __restrict__ nbrs, int* __restrict__ cnt) {
    int e = blockIdx.x * 256 + threadIdx.x;
    if (e < NE) atomicAdd(&cnt[nbrs[2 * e]], 1);
}
__global__ void __launch_bounds__(256) csr_scan(const int* __restrict__ cnt,
                                                int* __restrict__ off,
                                                int* __restrict__ pos) {
    __shared__ int base;
    __shared__ int wsum[8];
    if (threadIdx.x == 0) base = 0;
    __syncthreads();
    for (int c0 = 0; c0 < NN; c0 += 256) {
        int i = c0 + threadIdx.x;
        int v = (i < NN) ? cnt[i] : 0;
        int lane = threadIdx.x & 31, w = threadIdx.x >> 5;
        int x = v;
        #pragma unroll
        for (int o = 1; o < 32; o <<= 1) {
            int y = __shfl_up_sync(0xffffffffu, x, o);
            if (lane >= o) x += y;
        }
        if (lane == 31) wsum[w] = x;
        __syncthreads();
        int add = 0;
        #pragma unroll
        for (int k = 0; k < 8; k++) if (k < w) add += wsum[k];
        int incl = x + add;
        if (i < NN) {
            int excl = base + incl - v;
            off[i] = excl;
            pos[i] = excl;
        }
        __syncthreads();
        if (threadIdx.x == 255) base += incl;
        __syncthreads();
    }
    if (threadIdx.x == 0) off[NN] = base;
}
__global__ void csr_scatter(const int* __restrict__ nbrs, int* __restrict__ pos,
                            int* __restrict__ eidx) {
    int e = blockIdx.x * 256 + threadIdx.x;
    if (e < NE) {
        int p = atomicAdd(&pos[nbrs[2 * e]], 1);
        eidx[p] = e;
    }
}

// ================= segment-sum gather (no atomics) =================
__global__ void __launch_bounds__(128)
gather_kernel(const int* __restrict__ off, const int* __restrict__ eidx,
              const int* __restrict__ nbrs, const float* __restrict__ unit,
              const float* __restrict__ v_j, const float* __restrict__ eout,
              float* __restrict__ ds, float* __restrict__ dvout) {
    int i = blockIdx.x;
    int f = threadIdx.x;
    int s = off[i], t = off[i + 1];
    float a_ds = 0.f, a0 = 0.f, a1 = 0.f, a2 = 0.f;
    for (int p = s; p < t; p++) {
        int e = __ldg(eidx + p);
        int jj = __ldg(nbrs + 2 * e + 1);
        float ux = __ldg(unit + 3 * e), uy = __ldg(unit + 3 * e + 1), uz = __ldg(unit + 3 * e + 2);
        const float* o = eout + (size_t)e * 384;
        float s0 = o[f], s1 = o[128 + f], s2 = o[256 + f];
        const float* vj = v_j + ((size_t)jj * FF + f) * 3;
        a_ds += s1;
        a0 += s2 * ux + s0 * vj[0];
        a1 += s2 * uy + s0 * vj[1];
        a2 += s2 * uz + s0 * vj[2];
    }
    ds[(size_t)i * FF + f] = a_ds;
    float* dv = dvout + ((size_t)i * FF + f) * 3;
    dv[0] = a0; dv[1] = a1; dv[2] = a2;
}

// ================= B pre-permutation =================
__global__ void conv_B(const float* __restrict__ W, uint32_t* __restrict__ out,
                       int N, int nst, int Kreal, int Nld) {
    int i = blockIdx.x * 256 + threadIdx.x;
    int total = N * nst * 16;
    if (i >= total) return;
    int n = i / (nst * 16);
    int rem = i % (nst * 16);
    int s = rem >> 4, p = rem & 15;
    int bp = (p & 3) * 4 + (p >> 2);
    int k = s * 32 + bp * 2;
    float lo = (k < Kreal)     ? W[(size_t)k * Nld + n]       : 0.f;
    float hi = (k + 1 < Kreal) ? W[(size_t)(k + 1) * Nld + n] : 0.f;
    __half2 h = __floats2half2_rn(lo, hi);
    out[i] = *(uint32_t*)&h;
}

__global__ void __launch_bounds__(128) ln_kernel(const float* __restrict__ s,
                                                 const float* __restrict__ gam,
                                                 const float* __restrict__ bet,
                                                 float* __restrict__ x) {
    int n = blockIdx.x, t = threadIdx.x;
    float v = s[(size_t)n * FF + t];
    float s1 = v, s2 = v * v;
    #pragma unroll
    for (int o = 16; o; o >>= 1) {
        s1 += __shfl_down_sync(0xffffffffu, s1, o);
        s2 += __shfl_down_sync(0xffffffffu, s2, o);
    }
    __shared__ float p1[4], p2[4], mv[2];
    if ((t & 31) == 0) { p1[t >> 5] = s1; p2[t >> 5] = s2; }
    __syncthreads();
    if (t == 0) {
        float a = p1[0] + p1[1] + p1[2] + p1[3];
        float c = p2[0] + p2[1] + p2[2] + p2[3];
        float m = a / 128.f;
        mv[0] = m;
        mv[1] = rsqrtf(c / 128.f - m * m + 1e-5f);
    }
    __syncthreads();
    x[(size_t)n * FF + t] = (v - mv[0]) * mv[1] * gam[t] + bet[t];
}

__global__ void __launch_bounds__(256) edge_prep(const float* __restrict__ r,
                                                 __half* __restrict__ rbf,
                                                 float* __restrict__ unit) {
    int e = blockIdx.x * 256 + threadIdx.x;
    if (e >= NE) return;
    float x = __ldg(r + 3 * e), y = __ldg(r + 3 * e + 1), z = __ldg(r + 3 * e + 2);
    float d = sqrtf(x * x + y * y + z * z + 3e-15f);
    float inv = 1.f / d;
    unit[3 * e] = x * inv; unit[3 * e + 1] = y * inv; unit[3 * e + 2] = z * inv;
    const float width = 5.0f / 49.0f;
    const float gam = 0.5f / (width * width);
    __half2 buf[32];
    #pragma unroll
    for (int k2 = 0; k2 < 32; k2++) {
        int k0 = k2 * 2, k1 = k2 * 2 + 1;
        float d0 = d - (float)k0 * width;
        float d1 = d - (float)k1 * width;
        float v0 = (k0 < NRBF) ? __expf(-gam * d0 * d0) : 0.f;
        float v1 = (k1 < NRBF) ? __expf(-gam * d1 * d1) : 0.f;
        buf[k2] = __floats2half2_rn(v0, v1);
    }
    uint4* dst = (uint4*)(rbf + (size_t)e * RBFP);
    const uint4* src = (const uint4*)buf;
    #pragma unroll
    for (int q = 0; q < 8; q++) dst[q] = src[q];
}

// ================= qkv: fused 3-way f32x2 SGEMM =================
__global__ void __launch_bounds__(256, 2)
qkv_gemm(const float* __restrict__ Xin,
         const float* __restrict__ Wq, const float* __restrict__ Wk,
         const float* __restrict__ Wv,
         const float* __restrict__ bq, const float* __restrict__ bk,
         const float* __restrict__ bv,
         float* __restrict__ qkvout) {
    const int M = NN, N = 512, K = 128, lda = 128, ldc = 1536;
    int which = blockIdx.x >> 2;
    const float* B    = (which == 0) ? Wq : ((which == 1) ? Wk : Wv);
    const float* bias = (which == 0) ? bq : ((which == 1) ? bk : bv);
    float* C = qkvout + which * 512;
    int col0 = (blockIdx.x & 3) * 128;
    int row0 = blockIdx.y * 128;

    __shared__ float As[2][8][128];
    __shared__ float Bs[2][8][128];

    int t  = threadIdx.x;
    int ty = t >> 4, tx = t & 15;

    int arow = t >> 1;
    int acol = (t & 1) * 4;
    int am   = min(row0 + arow, M - 1);
    const float* Aptr = Xin + (size_t)am * lda + acol;

    int bk_ = t >> 5;
    int bn  = (t & 31) * 4;

    float4 ar, br;
    ar = *(const float4*)(Aptr);
    br = *(const float4*)(B + (size_t)bk_ * N + col0 + bn);

    As[0][acol + 0][arow] = ar.x;
    As[0][acol + 1][arow] = ar.y;
    As[0][acol + 2][arow] = ar.z;
    As[0][acol + 3][arow] = ar.w;
    *(float4*)&Bs[0][bk_][bn] = br;
    __syncthreads();

    ull acc[8][4];
    #pragma unroll
    for (int i = 0; i < 8; i++)
        #pragma unroll
        for (int j = 0; j < 4; j++) acc[i][j] = 0ULL;

    const int nstage = K >> 3;
    for (int s = 0; s < nstage; s++) {
        int cur = s & 1, nxt = cur ^ 1;
        bool more = (s + 1 < nstage);
        if (more) {
            int kk = (s + 1) << 3;
            ar = *(const float4*)(Aptr + kk);
            br = *(const float4*)(B + (size_t)(kk + bk_) * N + col0 + bn);
        }
        #pragma unroll
        for (int k = 0; k < 8; k++) {
            float4 a0 = *(float4*)&As[cur][k][ty * 8];
            float4 a1 = *(float4*)&As[cur][k][ty * 8 + 4];
            ulonglong2 b0 = *(ulonglong2*)&Bs[cur][k][tx * 8];
            ulonglong2 b1 = *(ulonglong2*)&Bs[cur][k][tx * 8 + 4];
            ull a2[8];
            PACK2(a2[0], a0.x); PACK2(a2[1], a0.y);
            PACK2(a2[2], a0.z); PACK2(a2[3], a0.w);
            PACK2(a2[4], a1.x); PACK2(a2[5], a1.y);
            PACK2(a2[6], a1.z); PACK2(a2[7], a1.w);
            #pragma unroll
            for (int i = 0; i < 8; i++) {
                FMA2(acc[i][0], a2[i], b0.x);
                FMA2(acc[i][1], a2[i], b0.y);
                FMA2(acc[i][2], a2[i], b1.x);
                FMA2(acc[i][3], a2[i], b1.y);
            }
        }
        if (more) {
            As[nxt][acol + 0][arow] = ar.x;
            As[nxt][acol + 1][arow] = ar.y;
            As[nxt][acol + 2][arow] = ar.z;
            As[nxt][acol + 3][arow] = ar.w;
            *(float4*)&Bs[nxt][bk_][bn] = br;
        }
        __syncthreads();
    }

    int colb = col0 + tx * 8;
    float4 bs0 = *(const float4*)(bias + colb);
    float4 bs1 = *(const float4*)(bias + colb + 4);
    #pragma unroll
    for (int i = 0; i < 8; i++) {
        int row = row0 + ty * 8 + i;
        if (row >= M) continue;
        float v[8];
        UNPACK2(v[0], v[1], acc[i][0]);
        UNPACK2(v[2], v[3], acc[i][1]);
        UNPACK2(v[4], v[5], acc[i][2]);
        UNPACK2(v[6], v[7], acc[i][3]);
        v[0] += bs0.x; v[1] += bs0.y; v[2] += bs0.z; v[3] += bs0.w;
        v[4] += bs1.x; v[5] += bs1.y; v[6] += bs1.z; v[7] += bs1.w;
        float* cp = C + (size_t)row * ldc + colb;
        *(float4*)cp       = make_float4(v[0], v[1], v[2], v[3]);
        *(float4*)(cp + 4) = make_float4(v[4], v[5], v[6], v[7]);
    }
}

// ================= attn + msg: warp-per-edge =================
__global__ void __launch_bounds__(256) attn_msg(const float* __restrict__ qkv,
                                                const __half* __restrict__ dkdv,
                                                const int* __restrict__ nbrs,
                                                __half* __restrict__ msg) {
    int e = blockIdx.x * 8 + (threadIdx.x >> 5);
    if (e >= NE) return;
    int l = threadIdx.x & 31;
    int i = __ldg(nbrs + 2 * e), j = __ldg(nbrs + 2 * e + 1);
    const float4* q4 = (const float4*)(qkv + (size_t)i * 1536);
    const float4* k4 = (const float4*)(qkv + (size_t)j * 1536 + 512);
    const float4* v4 = (const float4*)(qkv + (size_t)j * 1536 + 1024);
    const uint2* dk2 = (const uint2*)(dkdv + (size_t)e * 1024);
    const uint2* dv2 = dk2 + 128;

    float4 qv[4], kv[4], vv[4];
    uint2 dkv[4], dvv[4];
    #pragma unroll
    for (int h = 0; h < 4; h++) {
        int idx = h * 32 + l;
        qv[h] = q4[idx]; kv[h] = k4[idx]; vv[h] = v4[idx];
        dkv[h] = dk2[idx]; dvv[h] = dv2[idx];
    }
    float p[4];
    #pragma unroll
    for (int h = 0; h < 4; h++) {
        float2 f0 = __half22float2(*(__half2*)&dkv[h].x);
        float2 f1 = __half22float2(*(__half2*)&dkv[h].y);
        p[h] = qv[h].x * kv[h].x * f0.x + qv[h].y * kv[h].y * f0.y
             + qv[h].z * kv[h].z * f1.x + qv[h].w * kv[h].w * f1.y;
    }
    #pragma unroll
    for (int o = 16; o; o >>= 1)
        #pragma unroll
        for (int h = 0; h < 4; h++) p[h] += __shfl_xor_sync(0xffffffffu, p[h], o);

    __half* mrow = msg + (size_t)e * 512;
    #pragma unroll
    for (int h = 0; h < 4; h++) {
        float at = silu_f(p[h]);
        float2 g0 = __half22float2(*(__half2*)&dvv[h].x);
        float2 g1 = __half22float2(*(__half2*)&dvv[h].y);
        __half2 m0 = __floats2half2_rn(vv[h].x * g0.x * at, vv[h].y * g0.y * at);
        __half2 m1 = __floats2half2_rn(vv[h].z * g1.x * at, vv[h].w * g1.y * at);
        uint2 o2;
        o2.x = *(uint32_t*)&m0;
        o2.y = *(uint32_t*)&m1;
        *(uint2*)(mrow + h * 128 + l * 4) = o2;
    }
}

// ================= fp16 mma GEMM =================
// EPI=0 (dk or dv): silu + half store.  EPI=1 (big): biased float store to eout.
#define SROWU 20
#define ABUFU (128 * SROWU)

template <int EPI, int NSLICE>
__global__ void __launch_bounds__(256)
mma_fp16(const __half* __restrict__ A, const uint32_t* __restrict__ Bp,
         const float* __restrict__ bias, __half* __restrict__ C, int ldc,
         float* __restrict__ eout,
         int M, int lda, int nstage) {
    extern __shared__ uint32_t sm[];
    const uint32_t sA = smem_u32(sm);
    const uint32_t sB0 = sA + 2 * ABUFU * 4;

    const int tid = threadIdx.x;
    const int wid = tid >> 5, lid = tid & 31;
    const int gq = lid >> 2, tig = lid & 3;
    const int wM = wid >> 1, wN = wid & 1;
    const int row0 = (EPI == 1 ? blockIdx.x : blockIdx.y) * 128;
    const int n0s  = (EPI == 1 ? 0 : blockIdx.x * 128);

    float acc[NSLICE][2][8][4];
    #pragma unroll
    for (int s = 0; s < NSLICE; s++)
        #pragma unroll
        for (int a = 0; a < 2; a++)
            #pragma unroll
            for (int b = 0; b < 8; b++)
                #pragma unroll
                for (int c = 0; c < 4; c++) acc[s][a][b][c] = 0.f;

    const int arow = tid >> 1, ac2 = (tid & 1) * 2;
    const __half* aRow = A + (size_t)min(row0 + arow, M - 1) * lda;

    auto stage_A = [&](int s, int buf) {
        const __half* src = aRow + s * 32 + ac2 * 8;
        uint32_t dst = sA + (buf * ABUFU + arow * SROWU + ac2 * 4) * 4;
        CP_ASYNC16(dst, src);
        CP_ASYNC16(dst + 16, src + 8);
    };

    auto stage_B = [&](int s, int buf) {
        #pragma unroll
        for (int i = 0; i < NSLICE * 2; i++) {
            int cid = tid + i * 256;
            int sl = cid >> 9;
            int c  = cid & 511;
            int n = c >> 2, q = c & 3;
            int ng = (EPI == 1 ? sl * 128 : n0s) + n;
            const uint32_t* src = Bp + ((size_t)ng * nstage + s) * 16 + q * 4;
            uint32_t dst = sB0 + ((sl * 2 + buf) * ABUFU + n * SROWU + q * 4) * 4;
            CP_ASYNC16(dst, src);
        }
    };

    stage_A(0, 0);
    stage_B(0, 0);
    CP_COMMIT();
    CP_WAIT0();
    __syncthreads();

    for (int s = 0; s < nstage; s++) {
        int cur = s & 1;
        bool more = (s + 1 < nstage);
        if (more) {
            stage_A(s + 1, cur ^ 1);
            stage_B(s + 1, cur ^ 1);
            CP_COMMIT();
        }

        uint32_t af[2][2][4];
        const uint32_t* Ab = sm + cur * ABUFU;
        #pragma unroll
        for (int mf = 0; mf < 2; mf++) {
            int r0 = wM * 32 + mf * 16 + gq;
            const uint32_t* p0 = Ab + r0 * SROWU;
            const uint32_t* p1 = Ab + (r0 + 8) * SROWU;
            #pragma unroll
            for (int ks = 0; ks < 2; ks++) {
                af[mf][ks][0] = p0[tig + 8 * ks];
                af[mf][ks][1] = p1[tig + 8 * ks];
                af[mf][ks][2] = p0[tig + 4 + 8 * ks];
                af[mf][ks][3] = p1[tig + 4 + 8 * ks];
            }
        }
        const uint32_t* Bbase = sm + 2 * ABUFU + cur * ABUFU;
        #pragma unroll
        for (int sl = 0; sl < NSLICE; sl++) {
            const uint32_t* Bb = Bbase + sl * 2 * ABUFU;
            #pragma unroll
            for (int nf = 0; nf < 8; nf++) {
                int n = wN * 64 + nf * 8 + gq;
                uint4 bv = *(const uint4*)(Bb + n * SROWU + tig * 4);
                MMA_F16(acc[sl][0][nf], af[0][0][0], af[0][0][1], af[0][0][2], af[0][0][3], bv.x, bv.y);
                MMA_F16(acc[sl][1][nf], af[1][0][0], af[1][0][1], af[1][0][2], af[1][0][3], bv.x, bv.y);
                MMA_F16(acc[sl][0][nf], af[0][1][0], af[0][1][1], af[0][1][2], af[0][1][3], bv.z, bv.w);
                MMA_F16(acc[sl][1][nf], af[1][1][0], af[1][1][1], af[1][1][2], af[1][1][3], bv.z, bv.w);
            }
        }
        if (more) CP_WAIT0();
        __syncthreads();
    }

    if constexpr (EPI == 0) {
        #pragma unroll
        for (int mf = 0; mf < 2; mf++)
        #pragma unroll
        for (int rs = 0; rs < 2; rs++) {
            int r = row0 + wM * 32 + mf * 16 + rs * 8 + gq;
            if (r >= M) continue;
            #pragma unroll
            for (int nf = 0; nf < 8; nf++) {
                int nc = wN * 64 + nf * 8 + tig * 2;
                float v0 = silu_f(acc[0][mf][nf][rs * 2 + 0] + __ldg(bias + n0s + nc));
                float v1 = silu_f(acc[0][mf][nf][rs * 2 + 1] + __ldg(bias + n0s + nc + 1));
                *(__half2*)(C + (size_t)r * ldc + n0s + nc) = __floats2half2_rn(v0, v1);
            }
        }
    } else {
        #pragma unroll
        for (int mf = 0; mf < 2; mf++)
        #pragma unroll
        for (int rs = 0; rs < 2; rs++) {
            int e = row0 + wM * 32 + mf * 16 + rs * 8 + gq;
            if (e >= M) continue;
            float* o = eout + (size_t)e * 384;
            #pragma unroll
            for (int nf = 0; nf < 8; nf++) {
                int f = wN * 64 + nf * 8 + tig * 2;
                #pragma unroll
                for (int sl = 0; sl < NSLICE; sl++) {
                    float v0 = acc[sl][mf][nf][rs * 2 + 0] + __ldg(bias + sl * 128 + f);
                    float v1 = acc[sl][mf][nf][rs * 2 + 1] + __ldg(bias + sl * 128 + f + 1);
                    *(float2*)(o + sl * 128 + f) = make_float2(v0, v1);
                }
            }
        }
    }
}

// ================= launch =================
extern "C" void kernel_launch(void* const* d_in, const int* in_sizes, int n_in,
                              void* d_out, int out_size) {
    const float* s_j  = (const float*)d_in[0];
    const float* v_j  = (const float*)d_in[1];
    const float* r_ij = (const float*)d_in[2];
    const int*   nbrs = (const int*)  d_in[3];
    const float* ln_g = (const float*)d_in[4];
    const float* ln_b = (const float*)d_in[5];
    const float* Wq   = (const float*)d_in[6];
    const float* bq   = (const float*)d_in[7];
    const float* Wk   = (const float*)d_in[8];
    const float* bk   = (const float*)d_in[9];
    const float* Wv   = (const float*)d_in[10];
    const float* bv   = (const float*)d_in[11];
    const float* Wdk  = (const float*)d_in[12];
    const float* bdk  = (const float*)d_in[13];
    const float* Wdv  = (const float*)d_in[14];
    const float* bdv  = (const float*)d_in[15];
    const float* Wd   = (const float*)d_in[16];
    const float* bd   = (const float*)d_in[17];
    float* out = (float*)d_out;

    float *x, *qkv, *unit, *eout;
    __half *rbf, *dkdv, *msg;
    uint32_t *wdp, *wdkp, *wdvp;
    int *cnt, *off, *pos, *eidx;
    cudaGetSymbolAddress((void**)&x,    g_x);
    cudaGetSymbolAddress((void**)&qkv,  g_qkv);
    cudaGetSymbolAddress((void**)&rbf,  g_rbf);
    cudaGetSymbolAddress((void**)&unit, g_unit);
    cudaGetSymbolAddress((void**)&dkdv, g_dkdv);
    cudaGetSymbolAddress((void**)&msg,  g_msg);
    cudaGetSymbolAddress((void**)&eout, g_eout);
    cudaGetSymbolAddress((void**)&wdp,  g_wdp);
    cudaGetSymbolAddress((void**)&wdkp, g_wdkp);
    cudaGetSymbolAddress((void**)&wdvp, g_wdvp);
    cudaGetSymbolAddress((void**)&cnt,  g_cnt);
    cudaGetSymbolAddress((void**)&off,  g_off);
    cudaGetSymbolAddress((void**)&pos,  g_pos);
    cudaGetSymbolAddress((void**)&eidx, g_eidx);

    const int SMEM_DKDV = (2 + 1 * 2) * ABUFU * 4;   // 40960
    const int SMEM_BIG  = (2 + 3 * 2) * ABUFU * 4;   // 81920
    cudaFuncSetAttribute(mma_fp16<0, 1>, cudaFuncAttributeMaxDynamicSharedMemorySize, SMEM_DKDV);
    cudaFuncSetAttribute(mma_fp16<1, 3>, cudaFuncAttributeMaxDynamicSharedMemorySize, SMEM_BIG);

    // CSR build (independent of GEMM chain)
    zero_int<<<(NN + 255) / 256, 256>>>(cnt, NN);
    csr_hist<<<(NE + 255) / 256, 256>>>(nbrs, cnt);
    csr_scan<<<1, 256>>>(cnt, off, pos);
    csr_scatter<<<(NE + 255) / 256, 256>>>(nbrs, pos, eidx);

    // weight pre-permutation
    conv_B<<<(384 * 16 * 16 + 255) / 256, 256>>>(Wd,  wdp,  384, 16, 512, 384);
    conv_B<<<(512 * 2 * 16 + 255) / 256, 256>>>(Wdk, wdkp, 512, 2, 50, 512);
    conv_B<<<(512 * 2 * 16 + 255) / 256, 256>>>(Wdv, wdvp, 512, 2, 50, 512);

    ln_kernel<<<NN, 128>>>(s_j, ln_g, ln_b, x);

    dim3 gq3(12, (NN + 127) / 128);
    qkv_gemm<<<gq3, 256>>>(x, Wq, Wk, Wv, bq, bk, bv, qkv);

    edge_prep<<<(NE + 255) / 256, 256>>>(r_ij, rbf, unit);

    int mtiles = (NE + 127) / 128;   // 1954
    dim3 ge(4, mtiles);
    mma_fp16<0, 1><<<ge, 256, SMEM_DKDV>>>(rbf, wdkp, bdk, dkdv, 1024, nullptr,
                                           NE, RBFP, 2);
    mma_fp16<0, 1><<<ge, 256, SMEM_DKDV>>>(rbf, wdvp, bdv, dkdv + 512, 1024, nullptr,
                                           NE, RBFP, 2);

    attn_msg<<<(NE + 7) / 8, 256>>>(qkv, dkdv, nbrs, msg);

    mma_fp16<1, 3><<<mtiles, 256, SMEM_BIG>>>(msg, wdp, bd, nullptr, 0, eout,
                                              NE, 512, 16);

    gather_kernel<<<NN, 128>>>(off, eidx, nbrs, unit, v_j, eout,
                               out, out + NN * FF);
}